// round 9
// baseline (speedup 1.0000x reference)
#include <cuda_runtime.h>
#include <cstdint>

namespace {
constexpr int H_   = 16;
constexpr int N_   = 4096;
constexpr int D_   = 128;
constexpr int CHK  = 128;
constexpr int NBLK = 32;
constexpr int BHc  = 32;
constexpr int NCTA = 1024;

// ---- kdv (256 threads) ----
constexpr int KTH = 256;
constexpr int STT = 132;   // transposed-storage chunk stride [k][m]
constexpr int KF_TAB = 0;
constexpr int KF_V0  = 128;
constexpr int KF_K0  = KF_V0 + 32 * STT;
constexpr int KF_V1  = KF_K0 + 32 * STT;
constexpr int KF_K1  = KF_V1 + 32 * STT;
constexpr int SMEM_KDV = (KF_K1 + 32 * STT) * 4;      // 68,096 B

// ---- out (512 threads) ----
constexpr int OTH = 512;
constexpr int STQ = 136;   // q tile stride (8 mod 32 -> paired LDS.64 conflict-free)
constexpr int STB = 40;    // k/S chunk stride (8 mod 32)
constexpr int OF_TAB = 0;
constexpr int OF_Q   = 128;                  // q [128][STQ] raw fp32
constexpr int OF_FR  = OF_Q + 128 * STQ;     // scoresFrag: 16384 uint32 (fragment-ready)
constexpr int OF_K0  = OF_FR + 16384;        // k/S/v stream buffers
constexpr int OF_K1  = OF_K0 + 128 * STB;
constexpr int OF_S0  = OF_K1 + 128 * STB;
constexpr int OF_S1  = OF_S0 + 128 * STB;
constexpr int SMEM_OUT = (OF_S1 + 128 * STB) * 4;     // 217,600 B
}

__device__ float g_states[(size_t)NCTA * D_ * D_];

// ---------------------------------------------------------------------------
__device__ __forceinline__ uint32_t smem_u32(const void* p) {
    uint32_t a;
    asm("{ .reg .u64 t; cvta.to.shared.u64 t, %1; cvt.u32.u64 %0, t; }" : "=r"(a) : "l"(p));
    return a;
}
__device__ __forceinline__ uint32_t f2tf(float x) {
    uint32_t u;
    asm("cvt.rna.tf32.f32 %0, %1;" : "=r"(u) : "f"(x));
    return u;
}
__device__ __forceinline__ void cpa16(uint32_t dst, const float* src) {
    asm volatile("cp.async.cg.shared.global [%0], [%1], 16;" :: "r"(dst), "l"(src));
}
#define CP_COMMIT() asm volatile("cp.async.commit_group;" ::: "memory")
template <int N> __device__ __forceinline__ void cp_wait() {
    asm volatile("cp.async.wait_group %0;" :: "n"(N) : "memory");
}

__device__ __forceinline__ void mma8(float* d, const uint32_t* a, const uint32_t* b) {
    asm volatile(
        "mma.sync.aligned.m16n8k8.row.col.f32.tf32.tf32.f32 "
        "{%0,%1,%2,%3}, {%4,%5,%6,%7}, {%8,%9}, {%0,%1,%2,%3};"
        : "+f"(d[0]), "+f"(d[1]), "+f"(d[2]), "+f"(d[3])
        : "r"(a[0]), "r"(a[1]), "r"(a[2]), "r"(a[3]), "r"(b[0]), "r"(b[1]));
}

// ---------------------------------------------------------------------------
// Kernel 1 (unchanged from best): state contribution
//   g_states[bhc][e][d] = sum_s v[s][e] * k[s][d] * exp(-sl*(CHK-s))
// ---------------------------------------------------------------------------
__device__ __forceinline__ void fragB_Tc(const float* T, int n0, int k0, int g, int c, uint32_t* b) {
    const float* p = T + (k0 + c) * STT + n0 + g;
    b[0] = f2tf(p[0]);  b[1] = f2tf(p[4 * STT]);
}
__device__ __forceinline__ void fragA_Tsc(const float* T, int m0, int k0, int g, int c,
                                          float kd0, float kd1, uint32_t* a) {
    const float* p = T + (k0 + c) * STT + m0 + g;
    a[0] = f2tf(p[0] * kd0);  a[1] = f2tf(p[8] * kd0);
    p += 4 * STT;
    a[2] = f2tf(p[0] * kd1);  a[3] = f2tf(p[8] * kd1);
}
__device__ __forceinline__ void cp_t256(const float* __restrict__ base, int sc, uint32_t d) {
    #pragma unroll
    for (int it = 0; it < 4; it++) {
        int i = threadIdx.x + it * KTH;
        int r = i >> 5, c4 = (i & 31) << 2;
        cpa16(d + (uint32_t)(r * STT + c4) * 4, base + (sc * 32 + r) * 128 + c4);
    }
}

__global__ void __launch_bounds__(KTH, 2)
kdv_kernel(const float* __restrict__ k_g, const float* __restrict__ v_g,
           const float* __restrict__ s_g)
{
    extern __shared__ float sm[];
    const uint32_t smb = smem_u32(sm);
    float* tab = sm + KF_TAB;

    const int tid = threadIdx.x;
    const int bhc = blockIdx.x;
    const int bh = bhc >> 5, h = bh & (H_ - 1);
    const float sl = s_g[h];
    const size_t cbase = ((size_t)bh * N_ + (size_t)(bhc & 31) * CHK) * D_;

    if (tid < 128) tab[tid] = expf(-sl * (float)(CHK - tid));

    const float* kp = k_g + cbase;
    const float* vp = v_g + cbase;
    const uint32_t V[2] = { smb + KF_V0 * 4, smb + KF_V1 * 4 };
    const uint32_t K[2] = { smb + KF_K0 * 4, smb + KF_K1 * 4 };
    const float*   Vf[2] = { sm + KF_V0, sm + KF_V1 };
    const float*   Kf[2] = { sm + KF_K0, sm + KF_K1 };

    cp_t256(vp, 0, V[0]);
    cp_t256(kp, 0, K[0]);
    CP_COMMIT();

    const int lane = tid & 31, wid = tid >> 5;
    const int g = lane >> 2, c = lane & 3;
    const int m0w = (wid & 3) * 32, n0w = (wid >> 2) * 64;

    float acc[2][8][4];
    #pragma unroll
    for (int mt = 0; mt < 2; mt++)
        #pragma unroll
        for (int nt = 0; nt < 8; nt++)
            #pragma unroll
            for (int r = 0; r < 4; r++) acc[mt][nt][r] = 0.f;

    #pragma unroll 1
    for (int sc = 0; sc < 4; sc++) {
        if (sc < 3) {
            cp_t256(vp, sc + 1, V[(sc + 1) & 1]);
            cp_t256(kp, sc + 1, K[(sc + 1) & 1]);
            CP_COMMIT();
            cp_wait<1>();
        } else {
            cp_wait<0>();
        }
        __syncthreads();
        const float* A = Vf[sc & 1];
        const float* B = Kf[sc & 1];
        const int sbase = sc * 32;
        #pragma unroll
        for (int ks = 0; ks < 4; ks++) {
            const int k0 = ks * 8;
            const float kd0 = tab[sbase + k0 + c];
            const float kd1 = tab[sbase + k0 + c + 4];
            uint32_t af[2][4];
            fragA_Tsc(A, m0w,      k0, g, c, kd0, kd1, af[0]);
            fragA_Tsc(A, m0w + 16, k0, g, c, kd0, kd1, af[1]);
            #pragma unroll
            for (int nt = 0; nt < 8; nt++) {
                uint32_t bf[2];
                fragB_Tc(B, n0w + nt * 8, k0, g, c, bf);
                mma8(acc[0][nt], af[0], bf);
                mma8(acc[1][nt], af[1], bf);
            }
        }
        __syncthreads();
    }

    float* outp = g_states + (size_t)bhc * D_ * D_;
    #pragma unroll
    for (int mt = 0; mt < 2; mt++) {
        int r0 = m0w + mt * 16 + g;
        #pragma unroll
        for (int nt = 0; nt < 8; nt++) {
            int col = n0w + nt * 8 + 2 * c;
            *reinterpret_cast<float2*>(outp + r0 * 128 + col) =
                make_float2(acc[mt][nt][0], acc[mt][nt][1]);
            *reinterpret_cast<float2*>(outp + (r0 + 8) * 128 + col) =
                make_float2(acc[mt][nt][2], acc[mt][nt][3]);
        }
    }
}

// ---------------------------------------------------------------------------
// Kernel 2: exclusive decay scan over chunks (unchanged)
// ---------------------------------------------------------------------------
__global__ void __launch_bounds__(256, 1)
scan_kernel(const float* __restrict__ s_g)
{
    const int bh  = blockIdx.x >> 3;
    const int sli = blockIdx.x & 7;
    const int h   = bh & (H_ - 1);
    const float bd = expf(-s_g[h] * (float)CHK);
    const int tid = threadIdx.x;

    int u0 = tid,       d0 = u0 >> 2, q0 = u0 & 3;
    int u1 = tid + 256, d1 = u1 >> 2, q1 = u1 & 3;
    const int off0 = d0 * 32 + sli * 4 + q0;
    const int off1 = d1 * 32 + sli * 4 + q1;

    float4* base = reinterpret_cast<float4*>(g_states) + (size_t)bh * NBLK * (D_ * D_ / 4);
    float4 r0 = make_float4(0.f, 0.f, 0.f, 0.f), r1 = r0;
    for (int cc = 0; cc < NBLK; cc++) {
        float4* p = base + (size_t)cc * (D_ * D_ / 4);
        float4 t0 = p[off0], t1 = p[off1];
        p[off0] = r0;  p[off1] = r1;
        r0.x = bd * r0.x + t0.x;  r0.y = bd * r0.y + t0.y;
        r0.z = bd * r0.z + t0.z;  r0.w = bd * r0.w + t0.w;
        r1.x = bd * r1.x + t1.x;  r1.y = bd * r1.y + t1.y;
        r1.z = bd * r1.z + t1.z;  r1.w = bd * r1.w + t1.w;
    }
}

// ---------------------------------------------------------------------------
// Kernel 3 (512 threads, warp tile 16x64, grid 1024):
//   Phase A (fused, stream d): scores-acc = q.k^T ; inter-acc = q.S^T
//   Transform: mask/decay -> fragment-ready scoresFrag smem; inter *= qdec
//   Phase B (stream s): acc += scores @ v ; store o
// ---------------------------------------------------------------------------
__global__ void __launch_bounds__(OTH, 1)
out_kernel(const float* __restrict__ q_g, const float* __restrict__ k_g,
           const float* __restrict__ v_g, const float* __restrict__ s_g,
           float* __restrict__ o_g)
{
    extern __shared__ float sm[];
    const uint32_t smb = smem_u32(sm);
    float* tab = sm + OF_TAB;
    float* qt  = sm + OF_Q;
    uint32_t* frag = reinterpret_cast<uint32_t*>(sm + OF_FR);

    const int tid = threadIdx.x;
    const int bhc = blockIdx.x;
    const int bh = bhc >> 5, h = bh & (H_ - 1);
    const float sl = s_g[h];
    const size_t cbase = ((size_t)bh * N_ + (size_t)(bhc & 31) * CHK) * D_;

    if (tid < 128) tab[tid] = expf(-sl * (float)tid);

    const float* qp = q_g + cbase;
    const float* kp = k_g + cbase;
    const float* vp = v_g + cbase;
    const float* Sp = g_states + (size_t)bhc * D_ * D_;

    const uint32_t K[2] = { smb + OF_K0 * 4, smb + OF_K1 * 4 };
    const uint32_t S[2] = { smb + OF_S0 * 4, smb + OF_S1 * 4 };
    const float*   Kf[2] = { sm + OF_K0, sm + OF_K1 };
    const float*   Sf[2] = { sm + OF_S0, sm + OF_S1 };

    // ---- group 0: q full (to stride-STQ tile) + k0 + S0 ----
    {
        #pragma unroll
        for (int it = 0; it < 8; it++) {            // q: 4096 16B chunks
            int i = tid + it * OTH;
            int r = i >> 5, c4 = (i & 31) << 2;
            cpa16(smb + (uint32_t)(OF_Q + r * STQ + c4) * 4, qp + r * 128 + c4);
        }
        #pragma unroll
        for (int it = 0; it < 2; it++) {            // k chunk 0
            int i = tid + it * OTH;
            int r = i >> 3, c4 = (i & 7) << 2;
            cpa16(K[0] + (uint32_t)(r * STB + c4) * 4, kp + r * 128 + c4);
        }
        #pragma unroll
        for (int it = 0; it < 2; it++) {            // S chunk 0
            int i = tid + it * OTH;
            int r = i >> 3, c4 = (i & 7) << 2;
            cpa16(S[0] + (uint32_t)(r * STB + c4) * 4, Sp + r * 128 + c4);
        }
        CP_COMMIT();
    }

    const int lane = tid & 31, wid = tid >> 5;
    const int g = lane >> 2, c = lane & 3;
    const int mg = wid & 7, ng = wid >> 3;
    const int m0 = mg * 16, n0w = ng * 64;

    float acc1[8][4], acc2[8][4];
    #pragma unroll
    for (int nt = 0; nt < 8; nt++)
        #pragma unroll
        for (int r = 0; r < 4; r++) { acc1[nt][r] = 0.f; acc2[nt][r] = 0.f; }

    // ---- Phase A: fused GEMM1+GEMM2 over d-chunks ----
    #pragma unroll 1
    for (int dc = 0; dc < 4; dc++) {
        if (dc < 3) {
            const int nb = (dc + 1) & 1;
            #pragma unroll
            for (int it = 0; it < 2; it++) {
                int i = tid + it * OTH;
                int r = i >> 3, c4 = (i & 7) << 2;
                cpa16(K[nb] + (uint32_t)(r * STB + c4) * 4, kp + r * 128 + (dc + 1) * 32 + c4);
            }
            #pragma unroll
            for (int it = 0; it < 2; it++) {
                int i = tid + it * OTH;
                int r = i >> 3, c4 = (i & 7) << 2;
                cpa16(S[nb] + (uint32_t)(r * STB + c4) * 4, Sp + r * 128 + (dc + 1) * 32 + c4);
            }
            CP_COMMIT();
            cp_wait<1>();
        } else {
            cp_wait<0>();
        }
        __syncthreads();
        const float* Bk = Kf[dc & 1];
        const float* Bs = Sf[dc & 1];
        #pragma unroll
        for (int ks = 0; ks < 4; ks++) {
            const int k0 = ks * 8;
            const int dg = dc * 32 + k0;
            // A-frag from resident q (paired LDS.64), rows m0+g / m0+g+8
            uint32_t af[4];
            {
                float2 x = *reinterpret_cast<const float2*>(qt + (m0 + g) * STQ + dg + 2 * c);
                float2 y = *reinterpret_cast<const float2*>(qt + (m0 + g + 8) * STQ + dg + 2 * c);
                af[0] = f2tf(x.x); af[2] = f2tf(x.y);
                af[1] = f2tf(y.x); af[3] = f2tf(y.y);
            }
            #pragma unroll
            for (int nt = 0; nt < 8; nt++) {
                const int row = n0w + nt * 8 + g;
                uint32_t bk[2], bs[2];
                float2 zk = *reinterpret_cast<const float2*>(Bk + row * STB + k0 + 2 * c);
                float2 zs = *reinterpret_cast<const float2*>(Bs + row * STB + k0 + 2 * c);
                bk[0] = f2tf(zk.x); bk[1] = f2tf(zk.y);
                bs[0] = f2tf(zs.x); bs[1] = f2tf(zs.y);
                mma8(acc1[nt], af, bk);
                mma8(acc2[nt], af, bs);
            }
        }
        __syncthreads();
    }

    // ---- prefetch v chunk 0 into K-buffer region (stream bufs free now) ----
    {
        #pragma unroll
        for (int it = 0; it < 2; it++) {
            int i = tid + it * OTH;
            int r = i >> 5, c4 = (i & 31) << 2;
            cpa16(K[0] + (uint32_t)(r * STT + c4) * 4, vp + r * 128 + c4);
        }
        CP_COMMIT();
    }

    // ---- transform: scores -> fragment-ready smem; scale inter ----
    #pragma unroll
    for (int nt = 0; nt < 8; nt++) {
        const int j = ng * 8 + nt;
        const int s0 = n0w + nt * 8 + 2 * c;
        const int t0 = m0 + g, t1 = t0 + 8;
        float w00 = (t0 >= s0)     ? acc1[nt][0] * tab[t0 - s0]     : 0.f;
        float w01 = (t0 >= s0 + 1) ? acc1[nt][1] * tab[t0 - s0 - 1] : 0.f;
        float w10 = (t1 >= s0)     ? acc1[nt][2] * tab[t1 - s0]     : 0.f;
        float w11 = (t1 >= s0 + 1) ? acc1[nt][3] * tab[t1 - s0 - 1] : 0.f;
        // entry order = A-frag order: (a0,a1,a2,a3) = (w00, w10, w01, w11)
        uint4 e = make_uint4(f2tf(w00), f2tf(w10), f2tf(w01), f2tf(w11));
        *reinterpret_cast<uint4*>(frag + ((j * 8 + mg) * 32 + lane) * 4) = e;
    }
    {
        const float f0 = tab[m0 + g], f1 = tab[m0 + g + 8];
        #pragma unroll
        for (int nt = 0; nt < 8; nt++) {
            acc2[nt][0] *= f0;  acc2[nt][1] *= f0;
            acc2[nt][2] *= f1;  acc2[nt][3] *= f1;
        }
    }
    __syncthreads();   // scoresFrag visible to all warps

    // ---- Phase B: acc2 += scores @ v over s-chunks ----
    #pragma unroll 1
    for (int sc = 0; sc < 4; sc++) {
        if (sc < 3) {
            const int nb = (sc + 1) & 1;
            #pragma unroll
            for (int it = 0; it < 2; it++) {
                int i = tid + it * OTH;
                int r = i >> 5, c4 = (i & 31) << 2;
                cpa16(K[nb] + (uint32_t)(r * STT + c4) * 4,
                      vp + ((sc + 1) * 32 + r) * 128 + c4);
            }
            CP_COMMIT();
            cp_wait<1>();
        } else {
            cp_wait<0>();
        }
        __syncthreads();
        const float* Bv = Kf[sc & 1];
        #pragma unroll
        for (int ks = 0; ks < 4; ks++) {
            const int j = sc * 4 + ks;
            const int k0 = ks * 8;
            uint32_t af[4];
            *reinterpret_cast<uint4*>(af) =
                *reinterpret_cast<const uint4*>(frag + ((j * 8 + mg) * 32 + lane) * 4);
            #pragma unroll
            for (int nt = 0; nt < 8; nt++) {
                const int col = n0w + nt * 8 + g;
                uint32_t bf[2];
                bf[0] = f2tf(Bv[(k0 + 2 * c)     * STT + col]);
                bf[1] = f2tf(Bv[(k0 + 2 * c + 1) * STT + col]);
                mma8(acc2[nt], af, bf);
            }
        }
        __syncthreads();
    }

    // ---- epilogue ----
    float* oc = o_g + cbase;
    #pragma unroll
    for (int nt = 0; nt < 8; nt++) {
        int col = n0w + nt * 8 + 2 * c;
        *reinterpret_cast<float2*>(oc + (m0 + g) * 128 + col) =
            make_float2(acc2[nt][0], acc2[nt][1]);
        *reinterpret_cast<float2*>(oc + (m0 + g + 8) * 128 + col) =
            make_float2(acc2[nt][2], acc2[nt][3]);
    }
}

// ---------------------------------------------------------------------------
extern "C" void kernel_launch(void* const* d_in, const int* in_sizes, int n_in,
                              void* d_out, int out_size)
{
    const float* q = (const float*)d_in[0];
    const float* k = (const float*)d_in[1];
    const float* v = (const float*)d_in[2];
    const float* s = (const float*)d_in[3];
    float* o = (float*)d_out;

    cudaFuncSetAttribute(kdv_kernel, cudaFuncAttributeMaxDynamicSharedMemorySize, SMEM_KDV);
    cudaFuncSetAttribute(out_kernel, cudaFuncAttributeMaxDynamicSharedMemorySize, SMEM_OUT);

    kdv_kernel<<<NCTA, KTH, SMEM_KDV>>>(k, v, s);
    scan_kernel<<<BHc * 8, 256>>>(s);
    out_kernel<<<NCTA, OTH, SMEM_OUT>>>(q, k, v, s, o);
}

// round 10
// speedup vs baseline: 1.1159x; 1.1159x over previous
#include <cuda_runtime.h>
#include <cuda_fp16.h>
#include <cstdint>

namespace {
constexpr int H_   = 16;
constexpr int N_   = 4096;
constexpr int D_   = 128;
constexpr int CHK  = 128;
constexpr int NBLK = 32;
constexpr int BHc  = 32;
constexpr int NCTA = 1024;

// ---- kdv (256 threads) ----
constexpr int KTH = 256;
constexpr int STT = 132;   // transposed-storage chunk stride [k][m] (words)
constexpr int KF_TAB = 0;
constexpr int KF_V0  = 128;
constexpr int KF_K0  = KF_V0 + 32 * STT;
constexpr int KF_V1  = KF_K0 + 32 * STT;
constexpr int KF_K1  = KF_V1 + 32 * STT;
constexpr int SMEM_KDV = (KF_K1 + 32 * STT) * 4;      // 68,096 B

// ---- out (256 threads, 2 CTAs/SM) ----
constexpr int OTH = 256;
constexpr int STA = 36;    // A-chunk stride (q) [128][36]
constexpr int STB = 40;    // B-chunk stride (k/S) [128][40] (8 mod 32 -> LDS.64 phase-clean)
constexpr int STH = 136;   // scores stride in halves
// byte offsets
constexpr int OB_TAB = 0;                         // 128 floats
constexpr int OB_SCH = 512;                       // half[128*STH] = 34,816
constexpr int OB_A0  = OB_SCH + 128 * STH * 2;    // 35,328
constexpr int OB_A1  = OB_A0 + 128 * STA * 4;     // 53,760
constexpr int OB_B0  = OB_A1 + 128 * STA * 4;     // 72,192
constexpr int OB_B1  = OB_B0 + 128 * STB * 4;     // 92,672
constexpr int SMEM_OUT = OB_B1 + 128 * STB * 4;   // 113,152 B  (x2 = 226,304 <= 227,328)
}

__device__ float g_states[(size_t)NCTA * D_ * D_];

// ---------------------------------------------------------------------------
__device__ __forceinline__ uint32_t smem_u32(const void* p) {
    uint32_t a;
    asm("{ .reg .u64 t; cvta.to.shared.u64 t, %1; cvt.u32.u64 %0, t; }" : "=r"(a) : "l"(p));
    return a;
}
__device__ __forceinline__ uint32_t f2tf(float x) {
    uint32_t u;
    asm("cvt.rna.tf32.f32 %0, %1;" : "=r"(u) : "f"(x));
    return u;
}
__device__ __forceinline__ void cpa16(uint32_t dst, const float* src) {
    asm volatile("cp.async.cg.shared.global [%0], [%1], 16;" :: "r"(dst), "l"(src));
}
#define CP_COMMIT() asm volatile("cp.async.commit_group;" ::: "memory")
template <int N> __device__ __forceinline__ void cp_wait() {
    asm volatile("cp.async.wait_group %0;" :: "n"(N) : "memory");
}

__device__ __forceinline__ void mma8(float* d, const uint32_t* a, const uint32_t* b) {
    asm volatile(
        "mma.sync.aligned.m16n8k8.row.col.f32.tf32.tf32.f32 "
        "{%0,%1,%2,%3}, {%4,%5,%6,%7}, {%8,%9}, {%0,%1,%2,%3};"
        : "+f"(d[0]), "+f"(d[1]), "+f"(d[2]), "+f"(d[3])
        : "r"(a[0]), "r"(a[1]), "r"(a[2]), "r"(a[3]), "r"(b[0]), "r"(b[1]));
}

// ---------------------------------------------------------------------------
// Kernel 1 (unchanged, best known): state contribution
//   g_states[bhc][e][d] = sum_s v[s][e] * k[s][d] * exp(-sl*(CHK-s))
// Uses (c, c+4) k-labeling internally (self-consistent).
// ---------------------------------------------------------------------------
__device__ __forceinline__ void fragB_Tc(const float* T, int n0, int k0, int g, int c, uint32_t* b) {
    const float* p = T + (k0 + c) * STT + n0 + g;
    b[0] = f2tf(p[0]);  b[1] = f2tf(p[4 * STT]);
}
__device__ __forceinline__ void fragA_Tsc(const float* T, int m0, int k0, int g, int c,
                                          float kd0, float kd1, uint32_t* a) {
    const float* p = T + (k0 + c) * STT + m0 + g;
    a[0] = f2tf(p[0] * kd0);  a[1] = f2tf(p[8] * kd0);
    p += 4 * STT;
    a[2] = f2tf(p[0] * kd1);  a[3] = f2tf(p[8] * kd1);
}
__device__ __forceinline__ void cp_t256(const float* __restrict__ base, int sc, uint32_t d) {
    #pragma unroll
    for (int it = 0; it < 4; it++) {
        int i = threadIdx.x + it * KTH;
        int r = i >> 5, c4 = (i & 31) << 2;
        cpa16(d + (uint32_t)(r * STT + c4) * 4, base + (sc * 32 + r) * 128 + c4);
    }
}

__global__ void __launch_bounds__(KTH, 2)
kdv_kernel(const float* __restrict__ k_g, const float* __restrict__ v_g,
           const float* __restrict__ s_g)
{
    extern __shared__ float sm[];
    const uint32_t smb = smem_u32(sm);
    float* tab = sm + KF_TAB;

    const int tid = threadIdx.x;
    const int bhc = blockIdx.x;
    const int bh = bhc >> 5, h = bh & (H_ - 1);
    const float sl = s_g[h];
    const size_t cbase = ((size_t)bh * N_ + (size_t)(bhc & 31) * CHK) * D_;

    if (tid < 128) tab[tid] = expf(-sl * (float)(CHK - tid));

    const float* kp = k_g + cbase;
    const float* vp = v_g + cbase;
    const uint32_t V[2] = { smb + KF_V0 * 4, smb + KF_V1 * 4 };
    const uint32_t K[2] = { smb + KF_K0 * 4, smb + KF_K1 * 4 };
    const float*   Vf[2] = { sm + KF_V0, sm + KF_V1 };
    const float*   Kf[2] = { sm + KF_K0, sm + KF_K1 };

    cp_t256(vp, 0, V[0]);
    cp_t256(kp, 0, K[0]);
    CP_COMMIT();

    const int lane = tid & 31, wid = tid >> 5;
    const int g = lane >> 2, c = lane & 3;
    const int m0w = (wid & 3) * 32, n0w = (wid >> 2) * 64;

    float acc[2][8][4];
    #pragma unroll
    for (int mt = 0; mt < 2; mt++)
        #pragma unroll
        for (int nt = 0; nt < 8; nt++)
            #pragma unroll
            for (int r = 0; r < 4; r++) acc[mt][nt][r] = 0.f;

    #pragma unroll 1
    for (int sc = 0; sc < 4; sc++) {
        if (sc < 3) {
            cp_t256(vp, sc + 1, V[(sc + 1) & 1]);
            cp_t256(kp, sc + 1, K[(sc + 1) & 1]);
            CP_COMMIT();
            cp_wait<1>();
        } else {
            cp_wait<0>();
        }
        __syncthreads();
        const float* A = Vf[sc & 1];
        const float* B = Kf[sc & 1];
        const int sbase = sc * 32;
        #pragma unroll
        for (int ks = 0; ks < 4; ks++) {
            const int k0 = ks * 8;
            const float kd0 = tab[sbase + k0 + c];
            const float kd1 = tab[sbase + k0 + c + 4];
            uint32_t af[2][4];
            fragA_Tsc(A, m0w,      k0, g, c, kd0, kd1, af[0]);
            fragA_Tsc(A, m0w + 16, k0, g, c, kd0, kd1, af[1]);
            #pragma unroll
            for (int nt = 0; nt < 8; nt++) {
                uint32_t bf[2];
                fragB_Tc(B, n0w + nt * 8, k0, g, c, bf);
                mma8(acc[0][nt], af[0], bf);
                mma8(acc[1][nt], af[1], bf);
            }
        }
        __syncthreads();
    }

    float* outp = g_states + (size_t)bhc * D_ * D_;
    #pragma unroll
    for (int mt = 0; mt < 2; mt++) {
        int r0 = m0w + mt * 16 + g;
        #pragma unroll
        for (int nt = 0; nt < 8; nt++) {
            int col = n0w + nt * 8 + 2 * c;
            *reinterpret_cast<float2*>(outp + r0 * 128 + col) =
                make_float2(acc[mt][nt][0], acc[mt][nt][1]);
            *reinterpret_cast<float2*>(outp + (r0 + 8) * 128 + col) =
                make_float2(acc[mt][nt][2], acc[mt][nt][3]);
        }
    }
}

// ---------------------------------------------------------------------------
// Kernel 2: exclusive decay scan over chunks (unchanged)
// ---------------------------------------------------------------------------
__global__ void __launch_bounds__(256, 1)
scan_kernel(const float* __restrict__ s_g)
{
    const int bh  = blockIdx.x >> 3;
    const int sli = blockIdx.x & 7;
    const int h   = bh & (H_ - 1);
    const float bd = expf(-s_g[h] * (float)CHK);
    const int tid = threadIdx.x;

    int u0 = tid,       d0 = u0 >> 2, q0 = u0 & 3;
    int u1 = tid + 256, d1 = u1 >> 2, q1 = u1 & 3;
    const int off0 = d0 * 32 + sli * 4 + q0;
    const int off1 = d1 * 32 + sli * 4 + q1;

    float4* base = reinterpret_cast<float4*>(g_states) + (size_t)bh * NBLK * (D_ * D_ / 4);
    float4 r0 = make_float4(0.f, 0.f, 0.f, 0.f), r1 = r0;
    for (int cc = 0; cc < NBLK; cc++) {
        float4* p = base + (size_t)cc * (D_ * D_ / 4);
        float4 t0 = p[off0], t1 = p[off1];
        p[off0] = r0;  p[off1] = r1;
        r0.x = bd * r0.x + t0.x;  r0.y = bd * r0.y + t0.y;
        r0.z = bd * r0.z + t0.z;  r0.w = bd * r0.w + t0.w;
        r1.x = bd * r1.x + t1.x;  r1.y = bd * r1.y + t1.y;
        r1.z = bd * r1.z + t1.z;  r1.w = bd * r1.w + t1.w;
    }
}

// ---------------------------------------------------------------------------
// out helpers (paired (2c,2c+1) k-labeling throughout)
// ---------------------------------------------------------------------------
__device__ __forceinline__ void cp_ach(const float* __restrict__ base, int dc, uint32_t d) {
    #pragma unroll
    for (int it = 0; it < 4; it++) {
        int i = threadIdx.x + it * OTH;
        int r = i >> 3, c4 = (i & 7) << 2;
        cpa16(d + (uint32_t)(r * STA + c4) * 4, base + r * 128 + dc * 32 + c4);
    }
}
__device__ __forceinline__ void cp_bch(const float* __restrict__ base, int dc, uint32_t d) {
    #pragma unroll
    for (int it = 0; it < 4; it++) {
        int i = threadIdx.x + it * OTH;
        int r = i >> 3, c4 = (i & 7) << 2;
        cpa16(d + (uint32_t)(r * STB + c4) * 4, base + r * 128 + dc * 32 + c4);
    }
}
__device__ __forceinline__ void cp_vch(const float* __restrict__ base, int sc, uint32_t d) {
    #pragma unroll
    for (int it = 0; it < 4; it++) {
        int i = threadIdx.x + it * OTH;
        int r = i >> 5, c4 = (i & 31) << 2;
        cpa16(d + (uint32_t)(r * STT + c4) * 4, base + (sc * 32 + r) * 128 + c4);
    }
}

// one d-chunk of a K-major x K-major GEMM (A stride STA, B stride STB), paired k
__device__ __forceinline__ void gemm_KK(const float* A, const float* B,
                                        float acc[2][8][4], int m0w, int n0w,
                                        int g, int c) {
    #pragma unroll
    for (int ks = 0; ks < 4; ks++) {
        const int k0 = ks * 8;
        uint32_t af[2][4];
        #pragma unroll
        for (int mt = 0; mt < 2; mt++) {
            const float* pa = A + (m0w + mt * 16 + g) * STA + k0 + 2 * c;
            float2 x = *reinterpret_cast<const float2*>(pa);
            float2 y = *reinterpret_cast<const float2*>(pa + 8 * STA);
            af[mt][0] = f2tf(x.x); af[mt][2] = f2tf(x.y);
            af[mt][1] = f2tf(y.x); af[mt][3] = f2tf(y.y);
        }
        #pragma unroll
        for (int nt = 0; nt < 8; nt++) {
            const float* pb = B + (n0w + nt * 8 + g) * STB + k0 + 2 * c;
            float2 z = *reinterpret_cast<const float2*>(pb);
            uint32_t bf[2] = { f2tf(z.x), f2tf(z.y) };
            mma8(acc[0][nt], af[0], bf);
            mma8(acc[1][nt], af[1], bf);
        }
    }
}

// ---------------------------------------------------------------------------
// Kernel 3 (grid 1024, 256 threads, 2 CTAs/SM, warp tile 32x64):
//   GEMM1 (stream d): raw scores = q.k^T  -> fp16 scores smem (mask+decay)
//   GEMM2 (stream d): inter = q.S^T ; scale rows by exp(-sl t)
//   GEMM3 (stream s): o = inter + scores @ v
// ---------------------------------------------------------------------------
__global__ void __launch_bounds__(OTH, 2)
out_kernel(const float* __restrict__ q_g, const float* __restrict__ k_g,
           const float* __restrict__ v_g, const float* __restrict__ s_g,
           float* __restrict__ o_g)
{
    extern __shared__ char smc[];
    const uint32_t smb = smem_u32(smc);
    float* tab = reinterpret_cast<float*>(smc + OB_TAB);
    __half* sch = reinterpret_cast<__half*>(smc + OB_SCH);

    const int tid = threadIdx.x;
    const int bhc = blockIdx.x;
    const int bh = bhc >> 5, h = bh & (H_ - 1);
    const float sl = s_g[h];
    const size_t cbase = ((size_t)bh * N_ + (size_t)(bhc & 31) * CHK) * D_;

    if (tid < 128) tab[tid] = expf(-sl * (float)tid);

    const float* qp = q_g + cbase;
    const float* kp = k_g + cbase;
    const float* vp = v_g + cbase;
    const float* Sp = g_states + (size_t)bhc * D_ * D_;

    const uint32_t A[2] = { smb + OB_A0, smb + OB_A1 };
    const uint32_t B[2] = { smb + OB_B0, smb + OB_B1 };
    const float* Af[2] = { reinterpret_cast<float*>(smc + OB_A0),
                           reinterpret_cast<float*>(smc + OB_A1) };
    const float* Bf[2] = { reinterpret_cast<float*>(smc + OB_B0),
                           reinterpret_cast<float*>(smc + OB_B1) };

    const int lane = tid & 31, wid = tid >> 5;
    const int g = lane >> 2, c = lane & 3;
    const int m0w = (wid & 3) * 32, n0w = (wid >> 2) * 64;

    float acc[2][8][4];
    #pragma unroll
    for (int mt = 0; mt < 2; mt++)
        #pragma unroll
        for (int nt = 0; nt < 8; nt++)
            #pragma unroll
            for (int r = 0; r < 4; r++) acc[mt][nt][r] = 0.f;

    // ================= GEMM1: scores = q . k^T =================
    cp_ach(qp, 0, A[0]);
    cp_bch(kp, 0, B[0]);
    CP_COMMIT();
    #pragma unroll 1
    for (int dc = 0; dc < 4; dc++) {
        if (dc < 3) {
            cp_ach(qp, dc + 1, A[(dc + 1) & 1]);
            cp_bch(kp, dc + 1, B[(dc + 1) & 1]);
            CP_COMMIT();
            cp_wait<1>();
        } else {
            cp_wait<0>();
        }
        __syncthreads();
        gemm_KK(Af[dc & 1], Bf[dc & 1], acc, m0w, n0w, g, c);
        __syncthreads();
    }

    // prefetch GEMM2 chunk 0 while transforming
    cp_ach(qp, 0, A[0]);
    cp_bch(Sp, 0, B[0]);
    CP_COMMIT();

    // transform: mask + decay -> fp16 scores; zero acc
    #pragma unroll
    for (int mt = 0; mt < 2; mt++) {
        int t0 = m0w + mt * 16 + g, t1 = t0 + 8;
        #pragma unroll
        for (int nt = 0; nt < 8; nt++) {
            int s0 = n0w + nt * 8 + 2 * c;
            float w00 = (t0 >= s0)     ? acc[mt][nt][0] * tab[t0 - s0]     : 0.f;
            float w01 = (t0 >= s0 + 1) ? acc[mt][nt][1] * tab[t0 - s0 - 1] : 0.f;
            float w10 = (t1 >= s0)     ? acc[mt][nt][2] * tab[t1 - s0]     : 0.f;
            float w11 = (t1 >= s0 + 1) ? acc[mt][nt][3] * tab[t1 - s0 - 1] : 0.f;
            *reinterpret_cast<__half2*>(sch + t0 * STH + s0) = __floats2half2_rn(w00, w01);
            *reinterpret_cast<__half2*>(sch + t1 * STH + s0) = __floats2half2_rn(w10, w11);
            acc[mt][nt][0] = acc[mt][nt][1] = acc[mt][nt][2] = acc[mt][nt][3] = 0.f;
        }
    }

    // ================= GEMM2: inter = q . S^T (S[e][d]) =================
    #pragma unroll 1
    for (int dc = 0; dc < 4; dc++) {
        if (dc < 3) {
            cp_ach(qp, dc + 1, A[(dc + 1) & 1]);
            cp_bch(Sp, dc + 1, B[(dc + 1) & 1]);
            CP_COMMIT();
            cp_wait<1>();
        } else {
            cp_wait<0>();
        }
        __syncthreads();
        gemm_KK(Af[dc & 1], Bf[dc & 1], acc, m0w, n0w, g, c);
        __syncthreads();
    }

    // prefetch v chunk 0 (B bufs free), scale inter while it flies
    cp_vch(vp, 0, B[0]);
    CP_COMMIT();
    #pragma unroll
    for (int mt = 0; mt < 2; mt++) {
        float f0 = tab[m0w + mt * 16 + g];
        float f1 = tab[m0w + mt * 16 + g + 8];
        #pragma unroll
        for (int nt = 0; nt < 8; nt++) {
            acc[mt][nt][0] *= f0;  acc[mt][nt][1] *= f0;
            acc[mt][nt][2] *= f1;  acc[mt][nt][3] *= f1;
        }
    }

    // ================= GEMM3: o += scores @ v =================
    #pragma unroll 1
    for (int sc = 0; sc < 4; sc++) {
        if (sc < 3) {
            cp_vch(vp, sc + 1, B[(sc + 1) & 1]);
            CP_COMMIT();
            cp_wait<1>();
        } else {
            cp_wait<0>();
        }
        __syncthreads();
        const float* Bv = Bf[sc & 1];
        #pragma unroll
        for (int ks = 0; ks < 4; ks++) {
            const int k0 = ks * 8;                 // local s within chunk
            const int sg = sc * 32 + k0 + 2 * c;   // global s column in scores
            uint32_t af[2][4];
            #pragma unroll
            for (int mt = 0; mt < 2; mt++) {
                int t0 = m0w + mt * 16 + g;
                float2 fx = __half22float2(*reinterpret_cast<const __half2*>(sch + t0 * STH + sg));
                float2 fy = __half22float2(*reinterpret_cast<const __half2*>(sch + (t0 + 8) * STH + sg));
                af[mt][0] = __float_as_uint(fx.x); af[mt][2] = __float_as_uint(fx.y);
                af[mt][1] = __float_as_uint(fy.x); af[mt][3] = __float_as_uint(fy.y);
            }
            #pragma unroll
            for (int nt = 0; nt < 8; nt++) {
                const int col = n0w + nt * 8 + g;
                uint32_t bf[2];
                bf[0] = f2tf(Bv[(k0 + 2 * c)     * STT + col]);
                bf[1] = f2tf(Bv[(k0 + 2 * c + 1) * STT + col]);
                mma8(acc[0][nt], af[0], bf);
                mma8(acc[1][nt], af[1], bf);
            }
        }
        __syncthreads();
    }

    // ---- epilogue ----
    float* oc = o_g + cbase;
    #pragma unroll
    for (int mt = 0; mt < 2; mt++) {
        int r0 = m0w + mt * 16 + g;
        #pragma unroll
        for (int nt = 0; nt < 8; nt++) {
            int col = n0w + nt * 8 + 2 * c;
            *reinterpret_cast<float2*>(oc + r0 * 128 + col) =
                make_float2(acc[mt][nt][0], acc[mt][nt][1]);
            *reinterpret_cast<float2*>(oc + (r0 + 8) * 128 + col) =
                make_float2(acc[mt][nt][2], acc[mt][nt][3]);
        }
    }
}

// ---------------------------------------------------------------------------
extern "C" void kernel_launch(void* const* d_in, const int* in_sizes, int n_in,
                              void* d_out, int out_size)
{
    const float* q = (const float*)d_in[0];
    const float* k = (const float*)d_in[1];
    const float* v = (const float*)d_in[2];
    const float* s = (const float*)d_in[3];
    float* o = (float*)d_out;

    cudaFuncSetAttribute(kdv_kernel, cudaFuncAttributeMaxDynamicSharedMemorySize, SMEM_KDV);
    cudaFuncSetAttribute(out_kernel, cudaFuncAttributeMaxDynamicSharedMemorySize, SMEM_OUT);

    kdv_kernel<<<NCTA, KTH, SMEM_KDV>>>(k, v, s);
    scan_kernel<<<BHc * 8, 256>>>(s);
    out_kernel<<<NCTA, OTH, SMEM_OUT>>>(q, k, v, s, o);
}